// round 4
// baseline (speedup 1.0000x reference)
#include <cuda_runtime.h>

#define LOG2PI_F 1.8378770664093454f   // log(2*pi)
#define LOG2E_F  1.4426950408889634f   // log2(e)

typedef unsigned long long u64;

__device__ __forceinline__ u64 pack2(float lo, float hi) {
    u64 r; asm("mov.b64 %0, {%1, %2};" : "=l"(r) : "f"(lo), "f"(hi)); return r;
}
__device__ __forceinline__ void unpack2(u64 v, float& lo, float& hi) {
    asm("mov.b64 {%0, %1}, %2;" : "=f"(lo), "=f"(hi) : "l"(v));
}
__device__ __forceinline__ u64 add2(u64 a, u64 b) {
    u64 r; asm("add.rn.f32x2 %0, %1, %2;" : "=l"(r) : "l"(a), "l"(b)); return r;
}
__device__ __forceinline__ u64 mul2(u64 a, u64 b) {
    u64 r; asm("mul.rn.f32x2 %0, %1, %2;" : "=l"(r) : "l"(a), "l"(b)); return r;
}
__device__ __forceinline__ u64 fma2(u64 a, u64 b, u64 c) {
    u64 r; asm("fma.rn.f32x2 %0, %1, %2, %3;" : "=l"(r) : "l"(a), "l"(b), "l"(c)); return r;
}

// Each thread handles TWO batch points (b, b + B/2) for one keypoint k.
// All per-component math is packed across the two points with f32x2 ops.
// Shared params are stored pre-splatted so LDS.128 yields ready packed pairs.
__global__ __launch_bounds__(256)
void recovery_policy_kernel(
    const float* __restrict__ z,      // [B,K,2]
    const float* __restrict__ w,      // [K,C]
    const float* __restrict__ mu,     // [K,C,2]
    const float* __restrict__ cov,    // [K,C,2,2]
    const float* __restrict__ scale,  // [K,2]
    float* __restrict__ out,
    int B, int K, int C, int gradOff)
{
    const int k   = blockIdx.y;
    const int tid = threadIdx.x;

    // splatted packed params: sA = {(i00,i00),(i01,i01)}, sB = {(i11,i11),(c2,c2)},
    // sM = {(-m0,-m0),(-m1,-m1)}
    __shared__ ulonglong2 sA[128];
    __shared__ ulonglong2 sB[128];
    __shared__ ulonglong2 sM[128];
    __shared__ float2 s_scale;

    if (tid < C) {
        const int idx = k * C + tid;
        const float4 cv = ((const float4*)cov)[idx];     // a b c d
        const float det  = cv.x * cv.w - cv.y * cv.z;
        const float rdet = 1.0f / det;
        const float i00 =  cv.w * rdet;
        const float i01 = -cv.y * rdet;
        const float i11 =  cv.x * rdet;
        const float c2  = (logf(w[idx]) - 0.5f * logf(det) - LOG2PI_F) * LOG2E_F;
        const float2 m  = ((const float2*)mu)[idx];
        sA[tid] = make_ulonglong2(pack2(i00, i00), pack2(i01, i01));
        sB[tid] = make_ulonglong2(pack2(i11, i11), pack2(c2, c2));
        sM[tid] = make_ulonglong2(pack2(-m.x, -m.x), pack2(-m.y, -m.y));
    }
    if (tid == 0) s_scale = ((const float2*)scale)[k];
    __syncthreads();

    const int halfB = B >> 1;
    const int bA = blockIdx.x * blockDim.x + tid;
    if (bA >= halfB) return;
    const int bB = bA + halfB;

    const float2 zA = ((const float2*)z)[(size_t)bA * K + k];
    const float2 zB = ((const float2*)z)[(size_t)bB * K + k];
    const u64 z0p = pack2(zA.x, zB.x);   // x-coords of both points
    const u64 z1p = pack2(zA.y, zB.y);   // y-coords of both points

    const float nh = -0.5f * LOG2E_F;
    const u64 nhp = pack2(nh, nh);

    u64 pdfp = 0ULL, g0p = 0ULL, g1p = 0ULL;   // 0ULL == (0.0f, 0.0f)

    #pragma unroll 8
    for (int c = 0; c < C; c++) {
        const ulonglong2 A = sA[c];
        const ulonglong2 Bv = sB[c];
        const ulonglong2 M = sM[c];
        const u64 d0 = add2(z0p, M.x);
        const u64 d1 = add2(z1p, M.y);
        const u64 s0 = fma2(A.x, d0, mul2(A.y, d1));
        const u64 s1 = fma2(A.y, d0, mul2(Bv.x, d1));
        const u64 maha = fma2(d0, s0, mul2(d1, s1));
        const u64 arg  = fma2(maha, nhp, Bv.y);
        float aLo, aHi; unpack2(arg, aLo, aHi);
        const u64 ep = pack2(exp2f(aLo), exp2f(aHi));
        pdfp = add2(pdfp, ep);
        g0p  = fma2(ep, s0, g0p);
        g1p  = fma2(ep, s1, g1p);
    }

    float pdfA, pdfB, g0A, g0B, g1A, g1B;
    unpack2(pdfp, pdfA, pdfB);
    unpack2(g0p,  g0A,  g0B);
    unpack2(g1p,  g1A,  g1B);

    const float sx = s_scale.x, sy = s_scale.y;

    // point A epilogue
    {
        const float gx = -g0A * sx, gy = -g1A * sy;
        const float dn = 1.0f / (1.0f + expf(1.0f - 2.0f * pdfA));
        const float nrm = sqrtf(gx * gx + gy * gy);
        const float mag = expf((5500.0f - nrm) * (1.0f / 1100.0f));
        const float r = mag / nrm;
        ((float2*)out)[(size_t)bA * K + k] = make_float2(dn, dn);
        ((float2*)(out + gradOff))[(size_t)bA * K + k] = make_float2(gx * r, gy * r);
    }
    // point B epilogue
    {
        const float gx = -g0B * sx, gy = -g1B * sy;
        const float dn = 1.0f / (1.0f + expf(1.0f - 2.0f * pdfB));
        const float nrm = sqrtf(gx * gx + gy * gy);
        const float mag = expf((5500.0f - nrm) * (1.0f / 1100.0f));
        const float r = mag / nrm;
        ((float2*)out)[(size_t)bB * K + k] = make_float2(dn, dn);
        ((float2*)(out + gradOff))[(size_t)bB * K + k] = make_float2(gx * r, gy * r);
    }
}

extern "C" void kernel_launch(void* const* d_in, const int* in_sizes, int n_in,
                              void* d_out, int out_size)
{
    const float* z     = (const float*)d_in[0];  // [B,K,2]
    const float* w     = (const float*)d_in[1];  // [K,C]
    const float* mu    = (const float*)d_in[2];  // [K,C,2]
    const float* cov   = (const float*)d_in[3];  // [K,C,2,2]
    const float* scale = (const float*)d_in[4];  // [K,2]
    float* out = (float*)d_out;

    const int K = in_sizes[4] / 2;
    const int C = in_sizes[1] / K;
    const int B = in_sizes[0] / (2 * K);
    const int gradOff = out_size / 2;

    const int halfB = B / 2;
    dim3 grid((halfB + 255) / 256, K);
    recovery_policy_kernel<<<grid, 256>>>(z, w, mu, cov, scale, out,
                                          B, K, C, gradOff);
}

// round 6
// speedup vs baseline: 1.1055x; 1.1055x over previous
#include <cuda_runtime.h>

#define LOG2PI_F 1.8378770664093454f   // log(2*pi)
#define LOG2E_F  1.4426950408889634f   // log2(e)

typedef unsigned long long u64;

__device__ __forceinline__ u64 pack2(float lo, float hi) {
    u64 r; asm("mov.b64 %0, {%1, %2};" : "=l"(r) : "f"(lo), "f"(hi)); return r;
}
__device__ __forceinline__ void unpack2(u64 v, float& lo, float& hi) {
    asm("mov.b64 {%0, %1}, %2;" : "=f"(lo), "=f"(hi) : "l"(v));
}
__device__ __forceinline__ u64 add2(u64 a, u64 b) {
    u64 r; asm("add.rn.f32x2 %0, %1, %2;" : "=l"(r) : "l"(a), "l"(b)); return r;
}
__device__ __forceinline__ u64 mul2(u64 a, u64 b) {
    u64 r; asm("mul.rn.f32x2 %0, %1, %2;" : "=l"(r) : "l"(a), "l"(b)); return r;
}
__device__ __forceinline__ u64 fma2(u64 a, u64 b, u64 c) {
    u64 r; asm("fma.rn.f32x2 %0, %1, %2, %3;" : "=l"(r) : "l"(a), "l"(b), "l"(c)); return r;
}

// Each thread handles TWO batch points (b, b + B/2) for one keypoint k, with
// all per-component math packed across the two points via f32x2 ops.
// 128-thread blocks -> 2048 blocks for wave balance + latency hiding.
// Two independent accumulator chains break the serial-add dependency.
__global__ __launch_bounds__(128)
void recovery_policy_kernel(
    const float* __restrict__ z,      // [B,K,2]
    const float* __restrict__ w,      // [K,C]
    const float* __restrict__ mu,     // [K,C,2]
    const float* __restrict__ cov,    // [K,C,2,2]
    const float* __restrict__ scale,  // [K,2]
    float* __restrict__ out,
    int B, int K, int C, int gradOff)
{
    const int k   = blockIdx.y;
    const int tid = threadIdx.x;

    // splatted packed params: sA = {(i00,i00),(i01,i01)}, sB = {(i11,i11),(c2,c2)},
    // sM = {(-m0,-m0),(-m1,-m1)}
    __shared__ ulonglong2 sA[64];
    __shared__ ulonglong2 sB[64];
    __shared__ ulonglong2 sM[64];
    __shared__ float2 s_scale;

    if (tid < C) {
        const int idx = k * C + tid;
        const float4 cv = ((const float4*)cov)[idx];     // a b c d
        const float det  = cv.x * cv.w - cv.y * cv.z;
        const float rdet = 1.0f / det;
        const float i00 =  cv.w * rdet;
        const float i01 = -cv.y * rdet;
        const float i11 =  cv.x * rdet;
        const float c2  = (logf(w[idx]) - 0.5f * logf(det) - LOG2PI_F) * LOG2E_F;
        const float2 m  = ((const float2*)mu)[idx];
        sA[tid] = make_ulonglong2(pack2(i00, i00), pack2(i01, i01));
        sB[tid] = make_ulonglong2(pack2(i11, i11), pack2(c2, c2));
        sM[tid] = make_ulonglong2(pack2(-m.x, -m.x), pack2(-m.y, -m.y));
    }
    if (tid == 0) s_scale = ((const float2*)scale)[k];
    __syncthreads();

    const int halfB = B >> 1;
    const int bA = blockIdx.x * blockDim.x + tid;
    if (bA >= halfB) return;
    const int bB = bA + halfB;

    const float2 zA = __ldg(&((const float2*)z)[(size_t)bA * K + k]);
    const float2 zB = __ldg(&((const float2*)z)[(size_t)bB * K + k]);
    const u64 z0p = pack2(zA.x, zB.x);   // x-coords of both points
    const u64 z1p = pack2(zA.y, zB.y);   // y-coords of both points

    const float nh = -0.5f * LOG2E_F;
    const u64 nhp = pack2(nh, nh);

    // two independent accumulator chains
    u64 pdf0 = 0ULL, g00 = 0ULL, g10 = 0ULL;
    u64 pdf1 = 0ULL, g01 = 0ULL, g11 = 0ULL;

    #pragma unroll 16
    for (int c = 0; c < C; c += 2) {
        // chain 0
        {
            const ulonglong2 A  = sA[c];
            const ulonglong2 Bv = sB[c];
            const ulonglong2 M  = sM[c];
            const u64 d0 = add2(z0p, M.x);
            const u64 d1 = add2(z1p, M.y);
            const u64 s0 = fma2(A.x, d0, mul2(A.y, d1));
            const u64 s1 = fma2(A.y, d0, mul2(Bv.x, d1));
            const u64 maha = fma2(d0, s0, mul2(d1, s1));
            const u64 arg  = fma2(maha, nhp, Bv.y);
            float aLo, aHi; unpack2(arg, aLo, aHi);
            const u64 ep = pack2(exp2f(aLo), exp2f(aHi));
            pdf0 = add2(pdf0, ep);
            g00  = fma2(ep, s0, g00);
            g10  = fma2(ep, s1, g10);
        }
        // chain 1
        {
            const ulonglong2 A  = sA[c + 1];
            const ulonglong2 Bv = sB[c + 1];
            const ulonglong2 M  = sM[c + 1];
            const u64 d0 = add2(z0p, M.x);
            const u64 d1 = add2(z1p, M.y);
            const u64 s0 = fma2(A.x, d0, mul2(A.y, d1));
            const u64 s1 = fma2(A.y, d0, mul2(Bv.x, d1));
            const u64 maha = fma2(d0, s0, mul2(d1, s1));
            const u64 arg  = fma2(maha, nhp, Bv.y);
            float aLo, aHi; unpack2(arg, aLo, aHi);
            const u64 ep = pack2(exp2f(aLo), exp2f(aHi));
            pdf1 = add2(pdf1, ep);
            g01  = fma2(ep, s0, g01);
            g11  = fma2(ep, s1, g11);
        }
    }

    const u64 pdfp = add2(pdf0, pdf1);
    const u64 g0p  = add2(g00, g01);
    const u64 g1p  = add2(g10, g11);

    float pdfA, pdfB, g0A, g0B, g1A, g1B;
    unpack2(pdfp, pdfA, pdfB);
    unpack2(g0p,  g0A,  g0B);
    unpack2(g1p,  g1A,  g1B);

    const float sx = s_scale.x, sy = s_scale.y;

    // point A epilogue
    {
        const float gx = -g0A * sx, gy = -g1A * sy;
        const float dn = 1.0f / (1.0f + expf(1.0f - 2.0f * pdfA));
        const float nrm = sqrtf(gx * gx + gy * gy);
        const float mag = expf((5500.0f - nrm) * (1.0f / 1100.0f));
        const float r = mag / nrm;
        ((float2*)out)[(size_t)bA * K + k] = make_float2(dn, dn);
        ((float2*)(out + gradOff))[(size_t)bA * K + k] = make_float2(gx * r, gy * r);
    }
    // point B epilogue
    {
        const float gx = -g0B * sx, gy = -g1B * sy;
        const float dn = 1.0f / (1.0f + expf(1.0f - 2.0f * pdfB));
        const float nrm = sqrtf(gx * gx + gy * gy);
        const float mag = expf((5500.0f - nrm) * (1.0f / 1100.0f));
        const float r = mag / nrm;
        ((float2*)out)[(size_t)bB * K + k] = make_float2(dn, dn);
        ((float2*)(out + gradOff))[(size_t)bB * K + k] = make_float2(gx * r, gy * r);
    }
}

extern "C" void kernel_launch(void* const* d_in, const int* in_sizes, int n_in,
                              void* d_out, int out_size)
{
    const float* z     = (const float*)d_in[0];  // [B,K,2]
    const float* w     = (const float*)d_in[1];  // [K,C]
    const float* mu    = (const float*)d_in[2];  // [K,C,2]
    const float* cov   = (const float*)d_in[3];  // [K,C,2,2]
    const float* scale = (const float*)d_in[4];  // [K,2]
    float* out = (float*)d_out;

    const int K = in_sizes[4] / 2;
    const int C = in_sizes[1] / K;
    const int B = in_sizes[0] / (2 * K);
    const int gradOff = out_size / 2;

    const int halfB = B / 2;
    dim3 grid((halfB + 127) / 128, K);
    recovery_policy_kernel<<<grid, 128>>>(z, w, mu, cov, scale, out,
                                          B, K, C, gradOff);
}